// round 14
// baseline (speedup 1.0000x reference)
#include <cuda_runtime.h>
#include <cstdint>

// SyntacticGCN fused kernel GB300 (sm_103a)
// R14: R13 (occ 3, grid 444) + __ldcs evict-first policy on the 537MB read-once
//      stream (keeps L2 sets for W, cuts LTS thrash). Single-variable change.
// B=16, S=128, M=128, D=256, H=256

#define MM 128
#define DD 256
#define HH 256
#define NROWS 2048
#define NCTAS 444          // 3 * 148 SMs, one wave at occ 3
#define RMAX 5             // max rows per CTA (2048/444 -> 4 or 5)
#define NTHREADS 256

// dynamic smem layout (bytes)
#define PARTS_OFF 0
#define PARTS_SZ  (2 * 8 * 2 * DD * 4)        // 32768: double-buffered warp partials
#define HID_OFF   PARTS_SZ                    // 32768
#define HID_SZ    (RMAX * 2 * DD * 4)         // 10240
#define SMEM_DYN  (HID_OFF + HID_SZ)          // 43008 (x3 = 126 KB/SM)
// GEMM staging buffer (4*RMAX*64*16 = 20480 B) aliases PARTS

__device__ __forceinline__ double pack2(float a) {
    double d;
    asm("mov.b64 %0, {%1, %1};" : "=d"(d) : "f"(a));
    return d;
}
__device__ __forceinline__ double fma2(double a, double b, double c) {
    double d;
    asm("fma.rn.f32x2 %0, %1, %2, %3;" : "=d"(d) : "d"(a), "d"(b), "d"(c));
    return d;
}

__global__ __launch_bounds__(NTHREADS, 3)
void gcn_fused_kernel(const float* __restrict__ src,
                      const float* __restrict__ ngh,
                      const float* __restrict__ Wm,   // [2D, H] row-major
                      const float* __restrict__ bm,   // [H]
                      float* __restrict__ out)        // [NROWS, H]
{
    extern __shared__ __align__(16) char dsm[];
    float*   parts = (float*)(dsm + PARTS_OFF);   // [2][8][512]
    float*   hid   = (float*)(dsm + HID_OFF);     // [RMAX][512]
    double2* buf   = (double2*)(dsm + PARTS_OFF); // GEMM staging (aliases parts)
    __shared__ int cnts[2][8];

    const int tid  = threadIdx.x;
    const int warp = tid >> 5;
    const int lane = tid & 31;

    const int r0 = (int)(((long long)blockIdx.x * NROWS) / NCTAS);
    const int r1 = (int)(((long long)(blockIdx.x + 1) * NROWS) / NCTAS);
    const int nr = r1 - r0;                  // 4 or 5

    // ---------------- Phase 1: streaming, ONE sync per row, evict-first loads ----------------
    for (int r = 0; r < nr; ++r) {
        const int b = r & 1;
        const int row = r0 + r;
        const float4* sp = (const float4*)(src + (size_t)row * MM * DD);
        const float4* np = (const float4*)(ngh + (size_t)row * MM * DD);

        float4 sa0 = {0,0,0,0}, sa1 = {0,0,0,0}, na0 = {0,0,0,0}, na1 = {0,0,0,0};
        int cnt = 0;

        const int mbase = warp * 16;
        #pragma unroll 4
        for (int i = 0; i < 16; ++i) {
            const int moff = (mbase + i) * (DD / 4);
            // each LDG.128: 32 lanes x 16B contiguous = 4 full 128B lines; read-once -> .cs
            float4 s0 = __ldcs(sp + moff + lane);        // cols [0,128)
            float4 s1 = __ldcs(sp + moff + 32 + lane);   // cols [128,256)
            float4 n0 = __ldcs(np + moff + lane);
            float4 n1 = __ldcs(np + moff + 32 + lane);

            sa0.x += s0.x; sa0.y += s0.y; sa0.z += s0.z; sa0.w += s0.w;
            sa1.x += s1.x; sa1.y += s1.y; sa1.z += s1.z; sa1.w += s1.w;
            na0.x += n0.x; na0.y += n0.y; na0.z += n0.z; na0.w += n0.w;
            na1.x += n1.x; na1.y += n1.y; na1.z += n1.z; na1.w += n1.w;

            bool nz = (n0.x != 0.f) | (n0.y != 0.f) | (n0.z != 0.f) | (n0.w != 0.f) |
                      (n1.x != 0.f) | (n1.y != 0.f) | (n1.z != 0.f) | (n1.w != 0.f);
            if (__any_sync(0xffffffffu, nz)) cnt++;
        }

        float4* dst = (float4*)(parts + (b * 8 + warp) * (2 * DD));
        dst[lane]      = sa0;   // src cols [0,128)
        dst[32 + lane] = sa1;   // src cols [128,256)
        dst[64 + lane] = na0;   // neigh cols [0,128)
        dst[96 + lane] = na1;   // neigh cols [128,256)
        if (lane == 0) cnts[b][warp] = cnt;
        __syncthreads();   // buffer b's partials visible; buffer 1-b free for next row

        // combine: thread t owns src col t and neigh col t
        const float* pb = parts + b * 8 * (2 * DD);
        float ssum = 0.f, nsum = 0.f;
        #pragma unroll
        for (int w = 0; w < 8; ++w) {
            ssum += pb[w * (2 * DD) + tid];
            nsum += pb[w * (2 * DD) + DD + tid];
        }
        int ctot = 0;
        #pragma unroll
        for (int w = 0; w < 8; ++w) ctot += cnts[b][w];
        float inv = 1.0f / fmaxf((float)ctot, 1.0f);

        hid[r * (2 * DD) + tid]      = ssum;
        hid[r * (2 * DD) + DD + tid] = nsum * inv;
        // no second sync: row r+2's writes to buffer b are ordered after row r+1's
        // sync, which every thread reaches only after finishing this combine.
    }
    if (nr < RMAX) {
        hid[nr * (2 * DD) + tid]      = 0.f;
        hid[nr * (2 * DD) + DD + tid] = 0.f;
    }
    __syncthreads();   // hid complete; all parts reads done -> buf may alias

    // ---------------- Phase 2: FFMA2 GEMM, k-split x4 (R10/R13 verbatim) ----------------
    // thread = (jq, kq): j columns [4jq, 4jq+4), k range [128*kq, 128*kq+128)
    const int jq = tid & 63;
    const int kq = tid >> 6;
    const int k0 = kq * 128;

    double a01[RMAX], a23[RMAX];   // f32x2 accumulators: {j0,j1}, {j2,j3}
    #pragma unroll
    for (int r = 0; r < RMAX; ++r) { a01[r] = 0.0; a23[r] = 0.0; }

    #pragma unroll 1
    for (int k = 0; k < 128; k += 4) {
        // W rows k0+k .. k0+k+3, 4 j-columns each: LDG.128 as double2 (f32x2 pairs)
        const float* wb = Wm + (size_t)(k0 + k) * HH + 4 * jq;
        double2 w0 = __ldg((const double2*)(wb));
        double2 w1 = __ldg((const double2*)(wb + HH));
        double2 w2 = __ldg((const double2*)(wb + 2 * HH));
        double2 w3 = __ldg((const double2*)(wb + 3 * HH));

        #pragma unroll
        for (int r = 0; r < RMAX; ++r) {
            float4 h = *(const float4*)&hid[r * (2 * DD) + k0 + k];   // smem broadcast
            double h0 = pack2(h.x), h1 = pack2(h.y), h2 = pack2(h.z), h3 = pack2(h.w);
            a01[r] = fma2(h0, w0.x, a01[r]);  a23[r] = fma2(h0, w0.y, a23[r]);
            a01[r] = fma2(h1, w1.x, a01[r]);  a23[r] = fma2(h1, w1.y, a23[r]);
            a01[r] = fma2(h2, w2.x, a01[r]);  a23[r] = fma2(h2, w2.y, a23[r]);
            a01[r] = fma2(h3, w3.x, a01[r]);  a23[r] = fma2(h3, w3.y, a23[r]);
        }
    }

    // stage k-split partials: buf[kq][r][jq] = {j0,j1,j2,j3}  (STS.128, conflict-free)
    #pragma unroll
    for (int r = 0; r < RMAX; ++r)
        buf[(kq * RMAX + r) * 64 + jq] = make_double2(a01[r], a23[r]);
    __syncthreads();

    // ---------------- reduce kq partials + bias + leaky_relu ----------------
    {
        const int j  = tid;
        const float bj = __ldg(bm + j);
        const float* bf = (const float*)buf;
        #pragma unroll
        for (int r = 0; r < RMAX; ++r) {
            if (r < nr) {
                float v = bj;
                #pragma unroll
                for (int q = 0; q < 4; ++q)
                    v += bf[(q * RMAX + r) * 256 + j];
                out[(size_t)(r0 + r) * HH + j] = (v > 0.f) ? v : 0.01f * v;
            }
        }
    }
}

extern "C" void kernel_launch(void* const* d_in, const int* in_sizes, int n_in,
                              void* d_out, int out_size)
{
    const float* src = (const float*)d_in[0];   // [B,S,M,D]
    const float* ngh = (const float*)d_in[1];   // [B,S,M,D]
    const float* Wm  = (const float*)d_in[2];   // [2D,H]
    const float* bm  = (const float*)d_in[3];   // [H]
    float* out = (float*)d_out;                 // [B*S, H]

    cudaFuncSetAttribute(gcn_fused_kernel,
                         cudaFuncAttributeMaxDynamicSharedMemorySize, SMEM_DYN);
    gcn_fused_kernel<<<NCTAS, NTHREADS, SMEM_DYN>>>(src, ngh, Wm, bm, out);
}

// round 15
// speedup vs baseline: 1.1080x; 1.1080x over previous
#include <cuda_runtime.h>
#include <cstdint>

// SyntacticGCN fused kernel GB300 (sm_103a)
// R15: R10 base + zero-prefix early exit on neigh (ragged lens structure):
//      invalid neighbor rows are a zero suffix per (b,s); once a warp's 4-row
//      chunk ends in an all-zero row, the rest of its slice is zero -> skip.
//      Cuts ~34% of neigh DRAM traffic. src always fully read. FFMA2 tail.
// B=16, S=128, M=128, D=256, H=256

#define MM 128
#define DD 256
#define HH 256
#define NROWS 2048
#define NCTAS 296
#define RMAX 7
#define NTHREADS 256

// dynamic smem layout (bytes)
#define PARTS_OFF 0
#define PARTS_SZ  (2 * 8 * 2 * DD * 4)        // 32768: double-buffered warp partials
#define HID_OFF   PARTS_SZ                    // 32768
#define HID_SZ    (RMAX * 2 * DD * 4)         // 14336
#define SMEM_DYN  (HID_OFF + HID_SZ)          // 47104
// GEMM staging buffer (28672 B) aliases PARTS

__device__ __forceinline__ double pack2(float a) {
    double d;
    asm("mov.b64 %0, {%1, %1};" : "=d"(d) : "f"(a));
    return d;
}
__device__ __forceinline__ double fma2(double a, double b, double c) {
    double d;
    asm("fma.rn.f32x2 %0, %1, %2, %3;" : "=d"(d) : "d"(a), "d"(b), "d"(c));
    return d;
}

__global__ __launch_bounds__(NTHREADS, 2)
void gcn_fused_kernel(const float* __restrict__ src,
                      const float* __restrict__ ngh,
                      const float* __restrict__ Wm,   // [2D, H] row-major
                      const float* __restrict__ bm,   // [H]
                      float* __restrict__ out)        // [NROWS, H]
{
    extern __shared__ __align__(16) char dsm[];
    float*   parts = (float*)(dsm + PARTS_OFF);   // [2][8][512]
    float*   hid   = (float*)(dsm + HID_OFF);     // [RMAX][512]
    double2* buf   = (double2*)(dsm + PARTS_OFF); // GEMM staging (aliases parts)
    __shared__ int cnts[2][8];

    const int tid  = threadIdx.x;
    const int warp = tid >> 5;
    const int lane = tid & 31;

    const int r0 = (blockIdx.x * NROWS) / NCTAS;
    const int r1 = ((blockIdx.x + 1) * NROWS) / NCTAS;
    const int nr = r1 - r0;                  // 6 or 7

    // ---------------- Phase 1: streaming with neigh zero-suffix early exit ----------------
    // warp w owns m in [16w, 16w+16); lane owns cols [4l,4l+4) and [128+4l,+4).
    for (int r = 0; r < nr; ++r) {
        const int b = r & 1;
        const int row = r0 + r;
        const int mbase = warp * 16;
        const float4* sp = (const float4*)(src + (size_t)row * MM * DD) + mbase * (DD / 4);
        const float4* np = (const float4*)(ngh + (size_t)row * MM * DD) + mbase * (DD / 4);

        float4 sa0 = {0,0,0,0}, sa1 = {0,0,0,0}, na0 = {0,0,0,0}, na1 = {0,0,0,0};
        int  cnt   = 0;
        bool alive = true;   // warp-uniform: neigh slice still has valid rows

        #pragma unroll
        for (int c = 0; c < 4; ++c) {        // 4 chunks of 4 m-rows
            // src: always read (sum over all M)
            #pragma unroll
            for (int q = 0; q < 4; ++q) {
                const int moff = (c * 4 + q) * (DD / 4);
                float4 s0 = __ldcs(sp + moff + lane);        // cols [0,128)
                float4 s1 = __ldcs(sp + moff + 32 + lane);   // cols [128,256)
                sa0.x += s0.x; sa0.y += s0.y; sa0.z += s0.z; sa0.w += s0.w;
                sa1.x += s1.x; sa1.y += s1.y; sa1.z += s1.z; sa1.w += s1.w;
            }
            // neigh: read only while slice prefix is valid
            if (alive) {
                uint32_t votes = 0;
                #pragma unroll
                for (int q = 0; q < 4; ++q) {
                    const int moff = (c * 4 + q) * (DD / 4);
                    float4 n0 = __ldcs(np + moff + lane);
                    float4 n1 = __ldcs(np + moff + 32 + lane);
                    na0.x += n0.x; na0.y += n0.y; na0.z += n0.z; na0.w += n0.w;
                    na1.x += n1.x; na1.y += n1.y; na1.z += n1.z; na1.w += n1.w;
                    bool nz = (n0.x != 0.f) | (n0.y != 0.f) | (n0.z != 0.f) | (n0.w != 0.f) |
                              (n1.x != 0.f) | (n1.y != 0.f) | (n1.z != 0.f) | (n1.w != 0.f);
                    if (__any_sync(0xffffffffu, nz)) votes |= (1u << q);
                }
                cnt += __popc(votes);
                // last row of chunk invalid -> zero suffix: all later rows zero
                if (!(votes & 8u)) alive = false;
            }
        }

        float4* dst = (float4*)(parts + (b * 8 + warp) * (2 * DD));
        dst[lane]      = sa0;   // src cols [0,128)
        dst[32 + lane] = sa1;   // src cols [128,256)
        dst[64 + lane] = na0;   // neigh cols [0,128)
        dst[96 + lane] = na1;   // neigh cols [128,256)
        if (lane == 0) cnts[b][warp] = cnt;
        __syncthreads();   // buffer b's partials visible; buffer 1-b free for next row

        // combine: thread t owns src col t and neigh col t
        const float* pb = parts + b * 8 * (2 * DD);
        float ssum = 0.f, nsum = 0.f;
        #pragma unroll
        for (int w = 0; w < 8; ++w) {
            ssum += pb[w * (2 * DD) + tid];
            nsum += pb[w * (2 * DD) + DD + tid];
        }
        int ctot = 0;
        #pragma unroll
        for (int w = 0; w < 8; ++w) ctot += cnts[b][w];
        float inv = 1.0f / fmaxf((float)ctot, 1.0f);

        hid[r * (2 * DD) + tid]      = ssum;
        hid[r * (2 * DD) + DD + tid] = nsum * inv;
        // no second sync: row r+2's writes to buffer b are ordered after row r+1's
        // sync, which every thread reaches only after finishing this combine.
    }
    if (nr < RMAX) {
        hid[nr * (2 * DD) + tid]      = 0.f;
        hid[nr * (2 * DD) + DD + tid] = 0.f;
    }
    __syncthreads();   // hid complete; all parts reads done -> buf may alias

    // ---------------- Phase 2: FFMA2 GEMM, k-split x4 (R10 verbatim) ----------------
    // thread = (jq, kq): j columns [4jq, 4jq+4), k range [128*kq, 128*kq+128)
    const int jq = tid & 63;
    const int kq = tid >> 6;
    const int k0 = kq * 128;

    double a01[RMAX], a23[RMAX];   // f32x2 accumulators: {j0,j1}, {j2,j3}
    #pragma unroll
    for (int r = 0; r < RMAX; ++r) { a01[r] = 0.0; a23[r] = 0.0; }

    #pragma unroll 1
    for (int k = 0; k < 128; k += 4) {
        // W rows k0+k .. k0+k+3, 4 j-columns each: LDG.128 as double2 (f32x2 pairs)
        const float* wb = Wm + (size_t)(k0 + k) * HH + 4 * jq;
        double2 w0 = __ldg((const double2*)(wb));
        double2 w1 = __ldg((const double2*)(wb + HH));
        double2 w2 = __ldg((const double2*)(wb + 2 * HH));
        double2 w3 = __ldg((const double2*)(wb + 3 * HH));

        #pragma unroll
        for (int r = 0; r < RMAX; ++r) {
            float4 h = *(const float4*)&hid[r * (2 * DD) + k0 + k];   // smem broadcast
            double h0 = pack2(h.x), h1 = pack2(h.y), h2 = pack2(h.z), h3 = pack2(h.w);
            a01[r] = fma2(h0, w0.x, a01[r]);  a23[r] = fma2(h0, w0.y, a23[r]);
            a01[r] = fma2(h1, w1.x, a01[r]);  a23[r] = fma2(h1, w1.y, a23[r]);
            a01[r] = fma2(h2, w2.x, a01[r]);  a23[r] = fma2(h2, w2.y, a23[r]);
            a01[r] = fma2(h3, w3.x, a01[r]);  a23[r] = fma2(h3, w3.y, a23[r]);
        }
    }

    // stage k-split partials: buf[kq][r][jq] = {j0,j1,j2,j3}  (STS.128, conflict-free)
    #pragma unroll
    for (int r = 0; r < RMAX; ++r)
        buf[(kq * RMAX + r) * 64 + jq] = make_double2(a01[r], a23[r]);
    __syncthreads();

    // ---------------- reduce kq partials + bias + leaky_relu ----------------
    {
        const int j  = tid;
        const float bj = __ldg(bm + j);
        const float* bf = (const float*)buf;
        #pragma unroll
        for (int r = 0; r < RMAX; ++r) {
            if (r < nr) {
                float v = bj;
                #pragma unroll
                for (int q = 0; q < 4; ++q)
                    v += bf[(q * RMAX + r) * 256 + j];
                out[(size_t)(r0 + r) * HH + j] = (v > 0.f) ? v : 0.01f * v;
            }
        }
    }
}

extern "C" void kernel_launch(void* const* d_in, const int* in_sizes, int n_in,
                              void* d_out, int out_size)
{
    const float* src = (const float*)d_in[0];   // [B,S,M,D]
    const float* ngh = (const float*)d_in[1];   // [B,S,M,D]
    const float* Wm  = (const float*)d_in[2];   // [2D,H]
    const float* bm  = (const float*)d_in[3];   // [H]
    float* out = (float*)d_out;                 // [B*S, H]

    cudaFuncSetAttribute(gcn_fused_kernel,
                         cudaFuncAttributeMaxDynamicSharedMemorySize, SMEM_DYN);
    gcn_fused_kernel<<<NCTAS, NTHREADS, SMEM_DYN>>>(src, ngh, Wm, bm, out);
}